// round 17
// baseline (speedup 1.0000x reference)
#include <cuda_runtime.h>
#include <cuda_fp16.h>
#include <math.h>
#include <stdint.h>

// ---------------- problem constants ----------------
#define BATCH 2
#define T_    64
#define H_    32
#define W_    32
#define C_    192
#define L_    (T_*H_*W_)
#define ROWS  (BATCH*L_)        // 131072 rows
#define NH_   6
#define HD_   32
#define NTOK  128
#define NWIN  512
#define C3    576
#define CM_   768
#define SCALE_ 0.17677669529663687f

// ---------------- scratch ----------------
__device__ __half g_act  [(size_t)ROWS * C_];
__device__ __half g_qkvh [(size_t)ROWS * C3];
__device__ float  g_x2   [(size_t)ROWS * C_];
__device__ __half g_w    [442368];

// ---------------- helpers ----------------
__device__ __forceinline__ uint32_t smem_u32(const void* p) {
    uint32_t a;
    asm("{ .reg .u64 t; cvta.to.shared.u64 t, %1; cvt.u32.u64 %0, t; }" : "=r"(a) : "l"(p));
    return a;
}
#define CPA16(dst, src) asm volatile("cp.async.cg.shared.global [%0], [%1], 16;" :: "r"(dst), "l"(src))
#define CPA_COMMIT()    asm volatile("cp.async.commit_group;" ::: "memory")
#define CPA_WAIT0()     asm volatile("cp.async.wait_group 0;" ::: "memory")
#define LDM4(d0,d1,d2,d3,addr) \
    asm volatile("ldmatrix.sync.aligned.m8n8.x4.shared.b16 {%0,%1,%2,%3}, [%4];" \
        : "=r"(d0), "=r"(d1), "=r"(d2), "=r"(d3) : "r"(addr))
#define LDM4T(d0,d1,d2,d3,addr) \
    asm volatile("ldmatrix.sync.aligned.m8n8.x4.trans.shared.b16 {%0,%1,%2,%3}, [%4];" \
        : "=r"(d0), "=r"(d1), "=r"(d2), "=r"(d3) : "r"(addr))

__device__ __forceinline__ void mma_f16(float* c, const uint32_t* a, const uint32_t* b) {
    asm volatile("mma.sync.aligned.m16n8k16.row.col.f32.f16.f16.f32 "
        "{%0,%1,%2,%3},{%4,%5,%6,%7},{%8,%9},{%0,%1,%2,%3};"
        : "+f"(c[0]), "+f"(c[1]), "+f"(c[2]), "+f"(c[3])
        : "r"(a[0]), "r"(a[1]), "r"(a[2]), "r"(a[3]), "r"(b[0]), "r"(b[1]));
}

__device__ __forceinline__ size_t shifted_pos(int row) {
    int win = row >> 7, n = row & 127;
    int b  = win >> 9, widx = win & 511;
    int tb = widx >> 6, hb = (widx >> 3) & 7, wb = widx & 7;
    int ti = n >> 4,   hi = (n >> 2) & 3,    wi = n & 3;
    int t  = (tb*8 + ti + 4) & 63;
    int hh = (hb*4 + hi + 2) & 31;
    int ww = (wb*4 + wi + 2) & 31;
    return (size_t)b * L_ + (size_t)t * (H_*W_) + hh * W_ + ww;
}

// swizzled smem offset for a (row, 16B-chunk) pair, 32B logical rows, zero padding.
__device__ __forceinline__ uint32_t swz(int row, int ch) {
    return (uint32_t)(row * 32 + ((((row >> 2) & 1) ^ ch) << 4));
}

__device__ __forceinline__ float gelu_f(float v) {
    return 0.5f * v * (1.0f + erff(v * 0.70710678118654752f));
}

// ---------------- weight convert+transpose (all 4 weights) ----------------
__global__ void k_wconv_all(const float* __restrict__ qkv_w, const float* __restrict__ proj_w,
                            const float* __restrict__ fc1_w, const float* __restrict__ fc2_w,
                            __half* __restrict__ w) {
    int idx = blockIdx.x * 256 + threadIdx.x;
    if (idx >= 442368) return;
    const float* W; int K, N, off;
    if (idx < 110592)      { W = qkv_w;  K = 192; N = 576; off = 0; }
    else if (idx < 147456) { W = proj_w; K = 192; N = 192; off = 110592; }
    else if (idx < 294912) { W = fc1_w;  K = 192; N = 768; off = 147456; }
    else                   { W = fc2_w;  K = 768; N = 192; off = 294912; }
    int u = idx - off;
    int n = u / K, k = u - n * K;
    w[idx] = __float2half_rn(W[(size_t)k * N + n]);
}

// ---------------- A-resident GEMM (K=192), optional fused LN in A-staging ----------------
// MODE 0 (LNSTAGE, gathered):  oh = half(LN(x)*B + bias)          (qkv, NT=6)
// MODE 1:                      outf[pos] = res[pos] + A*B + bias  (proj+reverse+roll+residual, NT=2)
template<int MODE, int NT, bool LNSTAGE>
__global__ __launch_bounds__(256, 1) void k_gemm_ares(
    const __half* __restrict__ A, const float* __restrict__ Xf,
    const float* __restrict__ gvec, const float* __restrict__ bvec,
    const __half* __restrict__ Bw, const float* __restrict__ bias,
    float* __restrict__ outf, __half* __restrict__ oh,
    const float* __restrict__ res)
{
    extern __shared__ __align__(16) uint8_t smem[];
    const int tid = threadIdx.x;
    const int bm = blockIdx.x * 128;
    const uint32_t aH = smem_u32(smem);
    const uint32_t bB = aH + 49152;
    float* sg = (float*)(smem + 122880);
    float* sb = sg + 192;

    auto load_B = [&](int nt, int s) {
        const __half* bp = Bw + (size_t)(nt * 96) * 192;
        uint32_t base = bB + (uint32_t)(s * 36864);
        #pragma unroll
        for (int i = 0; i < 9; i++) {
            int u = i * 256 + tid;
            int cch = u / 192;
            int v = u - cch * 192;
            int row = v >> 1, h = v & 1;
            CPA16(base + (uint32_t)(cch * 3072) + swz(row, h),
                  bp + (size_t)row * 192 + cch * 16 + h * 8);
        }
        CPA_COMMIT();
    };

    load_B(0, 0);

    if (LNSTAGE) {
        if (tid < 192) { sg[tid] = gvec[tid]; sb[tid] = bvec[tid]; }
        int row = tid >> 1, hh = tid & 1;
        size_t srow = (MODE == 0) ? shifted_pos(bm + row) : (size_t)(bm + row);
        const float4* xr = (const float4*)(Xf + srow * 192 + hh * 96);
        float s1 = 0.f, s2 = 0.f;
        #pragma unroll
        for (int i = 0; i < 24; i++) {
            float4 t = __ldg(xr + i);
            s1 += t.x + t.y + t.z + t.w;
            s2 += t.x*t.x + t.y*t.y + t.z*t.z + t.w*t.w;
        }
        s1 += __shfl_xor_sync(0xffffffffu, s1, 1);
        s2 += __shfl_xor_sync(0xffffffffu, s2, 1);
        float mu   = s1 * (1.0f / 192.0f);
        float var  = s2 * (1.0f / 192.0f) - mu * mu;
        float rstd = rsqrtf(var + 1e-5f);
        __syncthreads();
        #pragma unroll
        for (int c16 = 0; c16 < 6; c16++) {
            int cch = hh * 6 + c16;
            #pragma unroll
            for (int h = 0; h < 2; h++) {
                float4 a = __ldg(xr + c16 * 4 + h * 2);
                float4 b = __ldg(xr + c16 * 4 + h * 2 + 1);
                int cb = hh * 96 + c16 * 16 + h * 8;
                __half2 o0 = __floats2half2_rn((a.x - mu) * rstd * sg[cb+0] + sb[cb+0],
                                               (a.y - mu) * rstd * sg[cb+1] + sb[cb+1]);
                __half2 o1 = __floats2half2_rn((a.z - mu) * rstd * sg[cb+2] + sb[cb+2],
                                               (a.w - mu) * rstd * sg[cb+3] + sb[cb+3]);
                __half2 o2 = __floats2half2_rn((b.x - mu) * rstd * sg[cb+4] + sb[cb+4],
                                               (b.y - mu) * rstd * sg[cb+5] + sb[cb+5]);
                __half2 o3 = __floats2half2_rn((b.z - mu) * rstd * sg[cb+6] + sb[cb+6],
                                               (b.w - mu) * rstd * sg[cb+7] + sb[cb+7]);
                uint4 st;
                st.x = *(uint32_t*)&o0; st.y = *(uint32_t*)&o1;
                st.z = *(uint32_t*)&o2; st.w = *(uint32_t*)&o3;
                *(uint4*)(smem + cch * 4096 + swz(row, h)) = st;
            }
        }
    } else {
        #pragma unroll
        for (int i = 0; i < 12; i++) {
            int u = i * 256 + tid;
            int cch = u >> 8;
            int row = (u >> 1) & 127;
            int h = u & 1;
            CPA16(aH + (uint32_t)(cch * 4096) + swz(row, h),
                  A + (size_t)(bm + row) * 192 + cch * 16 + h * 8);
        }
        CPA_COMMIT();
    }

    CPA_WAIT0();
    __syncthreads();

    const int wid = tid >> 5, lane = tid & 31;
    const int wm = wid & 3, wn = wid >> 2;
    const int arow0 = wm * 32 + (lane & 15);
    const int ach = lane >> 4;
    const int g = lane >> 3;
    const int brow0 = wn * 48 + ((g >> 1) << 3) + (lane & 7);
    const int bch = g & 1;

    #pragma unroll 1
    for (int nt = 0; nt < NT; nt++) {
        const int s = nt & 1;
        if (nt + 1 < NT) load_B(nt + 1, s ^ 1);

        float acc[2][6][4] = {};
        const uint32_t bbase = bB + (uint32_t)(s * 36864);
        #pragma unroll
        for (int c = 0; c < 12; c++) {
            uint32_t ah[2][4], bh[3][4];
            #pragma unroll
            for (int mt = 0; mt < 2; mt++) {
                uint32_t ad = (uint32_t)(c * 4096) + swz(arow0 + mt * 16, ach);
                LDM4(ah[mt][0], ah[mt][1], ah[mt][2], ah[mt][3], aH + ad);
            }
            #pragma unroll
            for (int p = 0; p < 3; p++) {
                uint32_t bd = bbase + (uint32_t)(c * 3072) + swz(brow0 + p * 16, bch);
                LDM4(bh[p][0], bh[p][1], bh[p][2], bh[p][3], bd);
            }
            #pragma unroll
            for (int mt = 0; mt < 2; mt++)
                #pragma unroll
                for (int p = 0; p < 3; p++)
                    #pragma unroll
                    for (int q = 0; q < 2; q++)
                        mma_f16(acc[mt][p * 2 + q], ah[mt], &bh[p][q * 2]);
        }

        const int bn = nt * 96;
        const float* biasp = bias + bn;
        #pragma unroll
        for (int mt = 0; mt < 2; mt++) {
            #pragma unroll
            for (int ro = 0; ro < 2; ro++) {
                int grow = bm + wm * 32 + mt * 16 + (lane >> 2) + ro * 8;
                size_t dstbase;
                if (MODE == 1) dstbase = shifted_pos(grow) * (size_t)192;
                else           dstbase = (size_t)grow * (NT * 96);
                #pragma unroll
                for (int nc = 0; nc < 6; nc++) {
                    int col = wn * 48 + nc * 8 + (lane & 3) * 2;
                    float v0 = acc[mt][nc][ro * 2 + 0] + __ldg(biasp + col);
                    float v1 = acc[mt][nc][ro * 2 + 1] + __ldg(biasp + col + 1);
                    size_t oi = dstbase + bn + col;
                    if (MODE == 0) {
                        *(__half2*)&oh[oi] = __floats2half2_rn(v0, v1);
                    } else {
                        float2 rv = *(const float2*)&res[oi];
                        float2 v; v.x = rv.x + v0; v.y = rv.y + v1;
                        *(float2*)&outf[oi] = v;
                    }
                }
            }
        }
        CPA_WAIT0();
        __syncthreads();
    }
}

// ---------------- fused MLP: LN2 -> fc1 -> GELU -> fc2 -> +x2, hidden lives in smem ----------------
// smem: A 48K | B1 2x36K | W2 2x36K | H 24K | gamma/beta 1.5K = 222720 bytes
__global__ __launch_bounds__(256, 1) void k_mlp(
    const float* __restrict__ x2,
    const float* __restrict__ gvec, const float* __restrict__ bvec,
    const __half* __restrict__ W1, const float* __restrict__ b1,
    const __half* __restrict__ W2, const float* __restrict__ b2,
    float* __restrict__ out)
{
    extern __shared__ __align__(16) uint8_t smem[];
    const int tid = threadIdx.x;
    const int bm = blockIdx.x * 128;
    const uint32_t aS  = smem_u32(smem);
    const uint32_t b1S = aS + 49152;
    const uint32_t w2S = aS + 122880;
    const uint32_t hS  = aS + 196608;
    float* sg = (float*)(smem + 221184);
    float* sb = sg + 192;

    auto load_B1 = [&](int ht, int s) {
        const __half* bp = W1 + (size_t)(ht * 96) * 192;
        uint32_t base = b1S + (uint32_t)(s * 36864);
        #pragma unroll
        for (int i = 0; i < 9; i++) {
            int u = i * 256 + tid;          // 12 chunks x 96 rows x 2 halves
            int cch = u / 192;
            int v = u - cch * 192;
            int row = v >> 1, h = v & 1;
            CPA16(base + (uint32_t)(cch * 3072) + swz(row, h),
                  bp + (size_t)row * 192 + cch * 16 + h * 8);
        }
        CPA_COMMIT();
    };
    auto load_W2 = [&](int ht, int s) {
        uint32_t base = w2S + (uint32_t)(s * 36864);
        #pragma unroll
        for (int i = 0; i < 9; i++) {
            int u = i * 256 + tid;          // 6 chunks x 192 rows x 2 halves
            int cch = u / 384;
            int v = u - cch * 384;
            int row = v >> 1, h = v & 1;
            CPA16(base + (uint32_t)(cch * 6144) + swz(row, h),
                  W2 + (size_t)row * 768 + ht * 96 + cch * 16 + h * 8);
        }
        CPA_COMMIT();
    };

    load_B1(0, 0);
    load_W2(0, 0);

    // fused LN2 staging into A smem
    if (tid < 192) { sg[tid] = gvec[tid]; sb[tid] = bvec[tid]; }
    {
        int row = tid >> 1, hh = tid & 1;
        const float4* xr = (const float4*)(x2 + (size_t)(bm + row) * 192 + hh * 96);
        float s1 = 0.f, s2 = 0.f;
        #pragma unroll
        for (int i = 0; i < 24; i++) {
            float4 t = __ldg(xr + i);
            s1 += t.x + t.y + t.z + t.w;
            s2 += t.x*t.x + t.y*t.y + t.z*t.z + t.w*t.w;
        }
        s1 += __shfl_xor_sync(0xffffffffu, s1, 1);
        s2 += __shfl_xor_sync(0xffffffffu, s2, 1);
        float mu   = s1 * (1.0f / 192.0f);
        float var  = s2 * (1.0f / 192.0f) - mu * mu;
        float rstd = rsqrtf(var + 1e-5f);
        __syncthreads();
        #pragma unroll
        for (int c16 = 0; c16 < 6; c16++) {
            int cch = hh * 6 + c16;
            #pragma unroll
            for (int h = 0; h < 2; h++) {
                float4 a = __ldg(xr + c16 * 4 + h * 2);
                float4 b = __ldg(xr + c16 * 4 + h * 2 + 1);
                int cb = hh * 96 + c16 * 16 + h * 8;
                __half2 o0 = __floats2half2_rn((a.x - mu) * rstd * sg[cb+0] + sb[cb+0],
                                               (a.y - mu) * rstd * sg[cb+1] + sb[cb+1]);
                __half2 o1 = __floats2half2_rn((a.z - mu) * rstd * sg[cb+2] + sb[cb+2],
                                               (a.w - mu) * rstd * sg[cb+3] + sb[cb+3]);
                __half2 o2 = __floats2half2_rn((b.x - mu) * rstd * sg[cb+4] + sb[cb+4],
                                               (b.y - mu) * rstd * sg[cb+5] + sb[cb+5]);
                __half2 o3 = __floats2half2_rn((b.z - mu) * rstd * sg[cb+6] + sb[cb+6],
                                               (b.w - mu) * rstd * sg[cb+7] + sb[cb+7]);
                uint4 st;
                st.x = *(uint32_t*)&o0; st.y = *(uint32_t*)&o1;
                st.z = *(uint32_t*)&o2; st.w = *(uint32_t*)&o3;
                *(uint4*)(smem + cch * 4096 + swz(row, h)) = st;
            }
        }
    }
    CPA_WAIT0();
    __syncthreads();

    const int wid = tid >> 5, lane = tid & 31;
    const int wm = wid & 3, wn = wid >> 2;
    const int arow0 = wm * 32 + (lane & 15);
    const int ach = lane >> 4;
    const int g = lane >> 3;
    const int brow48 = wn * 48 + ((g >> 1) << 3) + (lane & 7);
    const int brow96 = wn * 96 + ((g >> 1) << 3) + (lane & 7);
    const int bch = g & 1;

    float accO[2][12][4] = {};

    #pragma unroll 1
    for (int ht = 0; ht < 8; ht++) {
        const int s = ht & 1;
        if (ht + 1 < 8) { load_B1(ht + 1, s ^ 1); load_W2(ht + 1, s ^ 1); }

        // ---- fc1 tile GEMM: hidden[128, 96] ----
        float accH[2][6][4] = {};
        const uint32_t bbase = b1S + (uint32_t)(s * 36864);
        #pragma unroll
        for (int c = 0; c < 12; c++) {
            uint32_t ah[2][4], bh[3][4];
            #pragma unroll
            for (int mt = 0; mt < 2; mt++) {
                uint32_t ad = (uint32_t)(c * 4096) + swz(arow0 + mt * 16, ach);
                LDM4(ah[mt][0], ah[mt][1], ah[mt][2], ah[mt][3], aS + ad);
            }
            #pragma unroll
            for (int p = 0; p < 3; p++) {
                uint32_t bd = bbase + (uint32_t)(c * 3072) + swz(brow48 + p * 16, bch);
                LDM4(bh[p][0], bh[p][1], bh[p][2], bh[p][3], bd);
            }
            #pragma unroll
            for (int mt = 0; mt < 2; mt++)
                #pragma unroll
                for (int p = 0; p < 3; p++)
                    #pragma unroll
                    for (int q = 0; q < 2; q++)
                        mma_f16(accH[mt][p * 2 + q], ah[mt], &bh[p][q * 2]);
        }

        // ---- GELU + store hidden tile to smem (fp16, swizzled) ----
        const float* b1p = b1 + ht * 96;
        #pragma unroll
        for (int mt = 0; mt < 2; mt++) {
            #pragma unroll
            for (int ro = 0; ro < 2; ro++) {
                int row = wm * 32 + mt * 16 + (lane >> 2) + ro * 8;
                #pragma unroll
                for (int nc = 0; nc < 6; nc++) {
                    int col = wn * 48 + nc * 8 + (lane & 3) * 2;
                    float v0 = gelu_f(accH[mt][nc][ro * 2 + 0] + __ldg(b1p + col));
                    float v1 = gelu_f(accH[mt][nc][ro * 2 + 1] + __ldg(b1p + col + 1));
                    int cch = col >> 4, ch = (col >> 3) & 1;
                    __half2 hv = __floats2half2_rn(v0, v1);
                    *(__half2*)(smem + 196608 + cch * 4096 + swz(row, ch) + (col & 7) * 2) = hv;
                }
            }
        }
        __syncthreads();

        // ---- fc2 partial GEMM: out[128, 192] += H @ W2slice ----
        const uint32_t wbase = w2S + (uint32_t)(s * 36864);
        #pragma unroll
        for (int c = 0; c < 6; c++) {
            uint32_t ah[2][4], bh[6][4];
            #pragma unroll
            for (int mt = 0; mt < 2; mt++) {
                uint32_t ad = (uint32_t)(c * 4096) + swz(arow0 + mt * 16, ach);
                LDM4(ah[mt][0], ah[mt][1], ah[mt][2], ah[mt][3], hS + ad);
            }
            #pragma unroll
            for (int p = 0; p < 6; p++) {
                uint32_t bd = wbase + (uint32_t)(c * 6144) + swz(brow96 + p * 16, bch);
                LDM4(bh[p][0], bh[p][1], bh[p][2], bh[p][3], bd);
            }
            #pragma unroll
            for (int mt = 0; mt < 2; mt++)
                #pragma unroll
                for (int p = 0; p < 6; p++)
                    #pragma unroll
                    for (int q = 0; q < 2; q++)
                        mma_f16(accO[mt][p * 2 + q], ah[mt], &bh[p][q * 2]);
        }
        CPA_WAIT0();
        __syncthreads();
    }

    // ---- epilogue: out = x2 + accO + b2 ----
    #pragma unroll
    for (int mt = 0; mt < 2; mt++) {
        #pragma unroll
        for (int ro = 0; ro < 2; ro++) {
            int grow = bm + wm * 32 + mt * 16 + (lane >> 2) + ro * 8;
            size_t base = (size_t)grow * 192;
            #pragma unroll
            for (int p = 0; p < 6; p++) {
                #pragma unroll
                for (int q = 0; q < 2; q++) {
                    int col = wn * 96 + p * 16 + q * 8 + (lane & 3) * 2;
                    float v0 = accO[mt][p * 2 + q][ro * 2 + 0] + __ldg(b2 + col);
                    float v1 = accO[mt][p * 2 + q][ro * 2 + 1] + __ldg(b2 + col + 1);
                    float2 rv = *(const float2*)&x2[base + col];
                    float2 v; v.x = rv.x + v0; v.y = rv.y + v1;
                    *(float2*)&out[base + col] = v;
                }
            }
        }
    }
}

// ---------------- MMA flash attention: one block per (window, head), 4 warps ----------------
__global__ __launch_bounds__(128) void k_attn(const __half* __restrict__ qkvh,
                       const float* __restrict__ rpb_table,
                       __half* __restrict__ oh) {
    __shared__ __align__(16) __half Qs[128 * 40];
    __shared__ __align__(16) __half Ks[128 * 40];
    __shared__ __align__(16) __half Vs[128 * 40];
    __shared__ float rpbh[736];
    __shared__ int   cjl[128];

    const int blk = blockIdx.x;
    const int win = blk / NH_, head = blk % NH_;
    const int tid = threadIdx.x;
    const int w = tid >> 5, lane = tid & 31;
    const __half* wbase = qkvh + (size_t)win * NTOK * C3 + head * HD_;

    {
        int r = tid >> 2, cc = (tid & 3) * 8;
        for (int rr = r; rr < 128; rr += 32) {
            const __half* p = wbase + (size_t)rr * C3;
            *(uint4*)&Qs[rr * 40 + cc] = *(const uint4*)(p + cc);
            *(uint4*)&Ks[rr * 40 + cc] = *(const uint4*)(p + 192 + cc);
            *(uint4*)&Vs[rr * 40 + cc] = *(const uint4*)(p + 384 + cc);
        }
    }
    for (int t = tid; t < 735; t += 128) rpbh[t] = rpb_table[t * NH_ + head];
    const int widx = win & 511;
    {
        int j = tid;
        int tj = j >> 4, hj = (j >> 2) & 3, wj = j & 3;
        int tb = widx >> 6, hb = (widx >> 3) & 7, wb = widx & 7;
        int gt = tb * 8 + tj, gh = hb * 4 + hj, gw = wb * 4 + wj;
        int rt = (gt < 56) ? 0 : (gt < 60 ? 1 : 2);
        int rh = (gh < 28) ? 0 : (gh < 30 ? 1 : 2);
        int rw = (gw < 28) ? 0 : (gw < 30 ? 1 : 2);
        cjl[j] = ((tj * 15 + hj * 7 + wj) << 5) | (rt * 9 + rh * 3 + rw);
    }
    __syncthreads();

    const bool uni = ((widx >> 6) < 7) && (((widx >> 3) & 7) < 7) && ((widx & 7) < 7);

    int ibase[4], ilab[4];
    #pragma unroll
    for (int rr = 0; rr < 4; rr++) {
        int i = w * 32 + (rr >> 1) * 16 + (rr & 1) * 8 + (lane >> 2);
        int v = cjl[i];
        ibase[rr] = (v >> 5) + 129;
        ilab[rr]  = v & 31;
    }

    uint32_t aq[2][2][4];
    #pragma unroll
    for (int kt = 0; kt < 2; kt++)
        #pragma unroll
        for (int mt = 0; mt < 2; mt++) {
            uint32_t ad = smem_u32(&Qs[(w * 32 + mt * 16 + (lane & 15)) * 40 + kt * 16 + 8 * (lane >> 4)]);
            LDM4(aq[kt][mt][0], aq[kt][mt][1], aq[kt][mt][2], aq[kt][mt][3], ad);
        }

    float m[4] = {-1e30f, -1e30f, -1e30f, -1e30f};
    float sum[4] = {};
    float acc2[2][4][4] = {};

    for (int kb = 0; kb < 4; kb++) {
        uint32_t bk[4][4];
        #pragma unroll
        for (int jn = 0; jn < 4; jn++) {
            uint32_t ad = smem_u32(&Ks[(kb * 32 + jn * 8 + (lane & 7)) * 40 + 8 * (lane >> 3)]);
            LDM4(bk[jn][0], bk[jn][1], bk[jn][2], bk[jn][3], ad);
        }
        float sc[2][4][4] = {};
        #pragma unroll
        for (int mt = 0; mt < 2; mt++)
            #pragma unroll
            for (int jn = 0; jn < 4; jn++) {
                mma_f16(sc[mt][jn], aq[0][mt], &bk[jn][0]);
                mma_f16(sc[mt][jn], aq[1][mt], &bk[jn][2]);
            }
        int jb = kb * 32 + (lane & 3) * 2;
        #pragma unroll
        for (int jn = 0; jn < 4; jn++) {
            int v0 = cjl[jb + jn * 8];
            int v1 = cjl[jb + jn * 8 + 1];
            #pragma unroll
            for (int mt = 0; mt < 2; mt++)
                #pragma unroll
                for (int c = 0; c < 4; c++) {
                    int vv = (c & 1) ? v1 : v0;
                    int rr = mt * 2 + (c >> 1);
                    float s = sc[mt][jn][c] * SCALE_ + rpbh[ibase[rr] - (vv >> 5)];
                    if (!uni && ilab[rr] != (vv & 31)) s -= 100.0f;
                    sc[mt][jn][c] = s;
                }
        }
        float rmax[4] = {-1e30f, -1e30f, -1e30f, -1e30f};
        #pragma unroll
        for (int mt = 0; mt < 2; mt++)
            #pragma unroll
            for (int jn = 0; jn < 4; jn++)
                #pragma unroll
                for (int c = 0; c < 4; c++)
                    rmax[mt * 2 + (c >> 1)] = fmaxf(rmax[mt * 2 + (c >> 1)], sc[mt][jn][c]);
        #pragma unroll
        for (int rr = 0; rr < 4; rr++) {
            rmax[rr] = fmaxf(rmax[rr], __shfl_xor_sync(0xffffffffu, rmax[rr], 1));
            rmax[rr] = fmaxf(rmax[rr], __shfl_xor_sync(0xffffffffu, rmax[rr], 2));
        }
        float corr[4];
        #pragma unroll
        for (int rr = 0; rr < 4; rr++) {
            float nm = fmaxf(m[rr], rmax[rr]);
            corr[rr] = __expf(m[rr] - nm);
            m[rr] = nm;
            sum[rr] *= corr[rr];
        }
        #pragma unroll
        for (int mt = 0; mt < 2; mt++)
            #pragma unroll
            for (int vn = 0; vn < 4; vn++)
                #pragma unroll
                for (int c = 0; c < 4; c++)
                    acc2[mt][vn][c] *= corr[mt * 2 + (c >> 1)];
        uint32_t ap[2][2][4];
        #pragma unroll
        for (int mt = 0; mt < 2; mt++)
            #pragma unroll
            for (int jn = 0; jn < 4; jn++) {
                float p0 = __expf(sc[mt][jn][0] - m[mt * 2]);
                float p1 = __expf(sc[mt][jn][1] - m[mt * 2]);
                float p2 = __expf(sc[mt][jn][2] - m[mt * 2 + 1]);
                float p3 = __expf(sc[mt][jn][3] - m[mt * 2 + 1]);
                sum[mt * 2]     += p0 + p1;
                sum[mt * 2 + 1] += p2 + p3;
                __half2 hA = __floats2half2_rn(p0, p1);
                __half2 hB = __floats2half2_rn(p2, p3);
                ap[jn >> 1][mt][(jn & 1) * 2]     = *(uint32_t*)&hA;
                ap[jn >> 1][mt][(jn & 1) * 2 + 1] = *(uint32_t*)&hB;
            }
        #pragma unroll
        for (int vn = 0; vn < 4; vn++) {
            uint32_t bv[4];
            uint32_t ad = smem_u32(&Vs[(kb * 32 + 8 * (lane >> 3) + (lane & 7)) * 40 + vn * 8]);
            LDM4T(bv[0], bv[1], bv[2], bv[3], ad);
            #pragma unroll
            for (int mt = 0; mt < 2; mt++) {
                mma_f16(acc2[mt][vn], ap[0][mt], &bv[0]);
                mma_f16(acc2[mt][vn], ap[1][mt], &bv[2]);
            }
        }
    }
    float inv[4];
    #pragma unroll
    for (int rr = 0; rr < 4; rr++) {
        sum[rr] += __shfl_xor_sync(0xffffffffu, sum[rr], 1);
        sum[rr] += __shfl_xor_sync(0xffffffffu, sum[rr], 2);
        inv[rr] = 1.0f / sum[rr];
    }
    #pragma unroll
    for (int mt = 0; mt < 2; mt++) {
        size_t row0 = (size_t)(win * 128 + w * 32 + mt * 16 + (lane >> 2));
        #pragma unroll
        for (int vn = 0; vn < 4; vn++) {
            size_t o = row0 * C_ + head * HD_ + vn * 8 + (lane & 3) * 2;
            *(__half2*)&oh[o] = __floats2half2_rn(acc2[mt][vn][0] * inv[mt * 2],
                                                  acc2[mt][vn][1] * inv[mt * 2]);
            size_t o2 = o + 8 * C_;
            *(__half2*)&oh[o2] = __floats2half2_rn(acc2[mt][vn][2] * inv[mt * 2 + 1],
                                                   acc2[mt][vn][3] * inv[mt * 2 + 1]);
        }
    }
}

// ---------------- launch ----------------
#define ARES_SMEM 124416   // 48K (A) + 2*36K (B) + 1.5K (gamma/beta)
#define MLP_SMEM  222720   // 48K + 72K + 72K + 24K + 1.5K

extern "C" void kernel_launch(void* const* d_in, const int* in_sizes, int n_in,
                              void* d_out, int out_size) {
    const float* x      = (const float*)d_in[0];
    const float* n1g    = (const float*)d_in[1];
    const float* n1b    = (const float*)d_in[2];
    const float* qkv_w  = (const float*)d_in[3];
    const float* qkv_b  = (const float*)d_in[4];
    const float* rpb    = (const float*)d_in[5];
    const float* proj_w = (const float*)d_in[6];
    const float* proj_b = (const float*)d_in[7];
    const float* n2g    = (const float*)d_in[8];
    const float* n2b    = (const float*)d_in[9];
    const float* fc1_w  = (const float*)d_in[10];
    const float* fc1_b  = (const float*)d_in[11];
    const float* fc2_w  = (const float*)d_in[12];
    const float* fc2_b  = (const float*)d_in[13];
    float* out = (float*)d_out;

    __half *act, *w, *qkvh;
    float *x2;
    cudaGetSymbolAddress((void**)&act,  g_act);
    cudaGetSymbolAddress((void**)&w,    g_w);
    cudaGetSymbolAddress((void**)&qkvh, g_qkvh);
    cudaGetSymbolAddress((void**)&x2,   g_x2);

    cudaFuncSetAttribute(k_gemm_ares<0, 6, true>,  cudaFuncAttributeMaxDynamicSharedMemorySize, ARES_SMEM);
    cudaFuncSetAttribute(k_gemm_ares<1, 2, false>, cudaFuncAttributeMaxDynamicSharedMemorySize, ARES_SMEM);
    cudaFuncSetAttribute(k_mlp, cudaFuncAttributeMaxDynamicSharedMemorySize, MLP_SMEM);

    const int OQKV = 0, OPROJ = 110592, OFC1 = 147456, OFC2 = 294912;

    k_wconv_all<<<(442368 + 255)/256, 256>>>(qkv_w, proj_w, fc1_w, fc2_w, w);

    // 1) QKV GEMM with fused LN1 + shift + partition gather -> g_qkvh fp16
    k_gemm_ares<0, 6, true><<<ROWS/128, 256, ARES_SMEM>>>(
        nullptr, x, n1g, n1b, w + OQKV, qkv_b, nullptr, qkvh, nullptr);

    // 2) MMA windowed attention -> act fp16
    k_attn<<<BATCH * NWIN * NH_, 128>>>(qkvh, rpb, act);

    // 3) proj GEMM + reverse + roll + residual -> x2 fp32
    k_gemm_ares<1, 2, false><<<ROWS/128, 256, ARES_SMEM>>>(
        act, nullptr, nullptr, nullptr, w + OPROJ, proj_b, x2, nullptr, x);

    // 4) fused MLP: LN2 + fc1 + GELU + fc2 + residual -> d_out
    k_mlp<<<ROWS/128, 256, MLP_SMEM>>>(x2, n2g, n2b, w + OFC1, fc1_b, w + OFC2, fc2_b, out);
}